// round 11
// baseline (speedup 1.0000x reference)
#include <cuda_runtime.h>
#include <cuda_bf16.h>
#include <cstdint>

typedef unsigned long long ull;

#define B_TOTAL 131072
#define T_STEPS 30
#define DIN     88
#define H       20
#define NGATE   80

// ================= GEMM (layer-0 input projection, HMMA, persistent) =================
#define M_ROWS   (B_TOTAL * T_STEPS)      // 3932160
#define M_TILE   128
#define N_TILES  (M_ROWS / M_TILE)        // 30720
#define G_GRID   296                      // 2 CTAs/SM persistent
#define G_CTA    128
#define AST      104                      // A smem row stride in bf16 (208 B)
#define BST      104
#define CST      84                       // C stage row stride in f32 (336 B, 16B-aligned)

// smem byte offsets
#define SO_AHI   512                      // 128 x 104 bf16 = 26624
#define SO_ALO   (SO_AHI + 26624)         // 27136
#define SO_BHI   (SO_ALO + 26624)         // 53760
#define SO_BLO   (SO_BHI + 16640)         // 70400
#define G_SMEM   (SO_BLO + 16640)         // 87040  (2 CTAs/SM = 174KB)
#define SO_CSTG  SO_AHI                   // C stage aliases A (dead after MMA sync); 128*336=43008 < 53248

// 1.26 GB scratch for xg[b*T + t][80] (rec-kernel gate order), fp32
__device__ float g_xg[(size_t)M_ROWS * NGATE];

// ---------------- helpers ----------------
__device__ __forceinline__ void split4(float4 f, ull& hi4, ull& lo4) {
    __nv_bfloat16 hx = __float2bfloat16_rn(f.x);
    __nv_bfloat16 hy = __float2bfloat16_rn(f.y);
    __nv_bfloat16 hz = __float2bfloat16_rn(f.z);
    __nv_bfloat16 hw = __float2bfloat16_rn(f.w);
    __nv_bfloat16 lx = __float2bfloat16_rn(f.x - __bfloat162float(hx));
    __nv_bfloat16 ly = __float2bfloat16_rn(f.y - __bfloat162float(hy));
    __nv_bfloat16 lz = __float2bfloat16_rn(f.z - __bfloat162float(hz));
    __nv_bfloat16 lw = __float2bfloat16_rn(f.w - __bfloat162float(hw));
    hi4 = (ull)__bfloat16_as_ushort(hx) | ((ull)__bfloat16_as_ushort(hy) << 16)
        | ((ull)__bfloat16_as_ushort(hz) << 32) | ((ull)__bfloat16_as_ushort(hw) << 48);
    lo4 = (ull)__bfloat16_as_ushort(lx) | ((ull)__bfloat16_as_ushort(ly) << 16)
        | ((ull)__bfloat16_as_ushort(lz) << 32) | ((ull)__bfloat16_as_ushort(lw) << 48);
}

__device__ __forceinline__ void mma16816(float* d,
                                         uint32_t a0, uint32_t a1, uint32_t a2, uint32_t a3,
                                         uint32_t b0, uint32_t b1) {
    asm volatile(
        "mma.sync.aligned.m16n8k16.row.col.f32.bf16.bf16.f32 "
        "{%0,%1,%2,%3}, {%4,%5,%6,%7}, {%8,%9}, {%0,%1,%2,%3};"
        : "+f"(d[0]), "+f"(d[1]), "+f"(d[2]), "+f"(d[3])
        : "r"(a0), "r"(a1), "r"(a2), "r"(a3), "r"(b0), "r"(b1));
}

// natural gate row n -> rec-layout position j (inverse of the rec permutation)
__device__ __forceinline__ int inv_perm(int n) {
    int g2 = n / 20, r = n % 20, v = r / 5, u = r % 5;
    return v * 20 + g2 * 5 + u;
}

// ---------------- persistent GEMM kernel (EXACT R10 version, ~770us measured) ----------------
__global__ void __launch_bounds__(G_CTA, 2)
xg_gemm_kernel(const float* __restrict__ x, const float* __restrict__ Wih0,
               const float* __restrict__ bih0, const float* __restrict__ bhh0)
{
    extern __shared__ char smem[];
    const int tid = threadIdx.x;
    const int warp = tid >> 5, lane = tid & 31;
    const int gid = lane >> 2, tg = lane & 3;

    // ---- one-time: B hi/lo staging (natural gate-row order) ----
    if (tid < NGATE) {
        char* bhi = smem + SO_BHI + tid * (BST * 2);
        char* blo = smem + SO_BLO + tid * (BST * 2);
        const float4* wr = (const float4*)(Wih0 + tid * DIN);
        float4 wv[22];
        #pragma unroll
        for (int q = 0; q < 22; q++) wv[q] = wr[q];
        #pragma unroll
        for (int q = 0; q < 22; q++) {
            ull hi4, lo4;
            split4(wv[q], hi4, lo4);
            *(ull*)(bhi + q * 8) = hi4;
            *(ull*)(blo + q * 8) = lo4;
        }
        *(ull*)(bhi + 176) = 0; *(ull*)(bhi + 184) = 0;
        *(ull*)(blo + 176) = 0; *(ull*)(blo + 184) = 0;
    }

    // ---- per-thread constants: bias (natural col order) + inv-perm offsets ----
    float2 bias_r[10];
    int ipa[10], ipb[10];
    #pragma unroll
    for (int nf = 0; nf < 10; nf++) {
        int n0 = nf * 8 + tg * 2;
        bias_r[nf] = make_float2(bih0[n0] + bhh0[n0], bih0[n0 + 1] + bhh0[n0 + 1]);
        ipa[nf] = inv_perm(n0);
        ipb[nf] = inv_perm(n0 + 1);
    }

    // ---- coalesced prefetch of first tile (float4 index q*128+tid) ----
    int tile = blockIdx.x;
    float4 xr[22];
    if (tile < N_TILES) {
        const float4* xp = (const float4*)(x + (size_t)tile * M_TILE * DIN);
        #pragma unroll
        for (int q = 0; q < 22; q++) xr[q] = xp[q * 128 + tid];
    }
    __syncthreads();

    #pragma unroll 1
    for (; tile < N_TILES; tile += G_GRID) {
        // ---- phase 1: split + scatter-store A (regs hold coalesced chunks) ----
        #pragma unroll
        for (int q = 0; q < 22; q++) {
            int e = q * 512 + tid * 4;          // element index within 128x88 tile
            int r = e / 88;
            int cc = e - r * 88;
            int addr = r * (AST * 2) + cc * 2;  // bytes
            ull hi4, lo4;
            split4(xr[q], hi4, lo4);
            *(ull*)(smem + SO_AHI + addr) = hi4;
            *(ull*)(smem + SO_ALO + addr) = lo4;
        }
        // re-zero pads (cstg alias clobbers them): thread tid owns row tid
        {
            char* ah = smem + SO_AHI + tid * (AST * 2);
            char* al = smem + SO_ALO + tid * (AST * 2);
            *(ull*)(ah + 176) = 0; *(ull*)(ah + 184) = 0;
            *(ull*)(al + 176) = 0; *(ull*)(al + 184) = 0;
        }
        __syncthreads();

        // ---- phase 2: coalesced prefetch of next tile (overlaps MMA) ----
        {
            int nxt = tile + G_GRID;
            if (nxt < N_TILES) {
                const float4* xp = (const float4*)(x + (size_t)nxt * M_TILE * DIN);
                #pragma unroll
                for (int q = 0; q < 22; q++) xr[q] = xp[q * 128 + tid];
            }
        }

        // ---- MMA mainloop: 6 ko steps, each fragment loaded ONCE ----
        float c[2][10][4];
        #pragma unroll
        for (int mf = 0; mf < 2; mf++)
            #pragma unroll
            for (int nf = 0; nf < 10; nf++)
                #pragma unroll
                for (int q = 0; q < 4; q++) c[mf][nf][q] = 0.f;

        #pragma unroll 1
        for (int ko6 = 0; ko6 < 6; ko6++) {
            const int kb = (ko6 * 16 + tg * 2) * 2;

            uint32_t bh[10][2], bl[10][2];
            #pragma unroll
            for (int nf = 0; nf < 10; nf++) {
                int n = nf * 8 + gid;
                const char* bph = smem + SO_BHI + n * (BST * 2) + kb;
                const char* bpl = smem + SO_BLO + n * (BST * 2) + kb;
                bh[nf][0] = *(const uint32_t*)(bph);
                bh[nf][1] = *(const uint32_t*)(bph + 16);
                bl[nf][0] = *(const uint32_t*)(bpl);
                bl[nf][1] = *(const uint32_t*)(bpl + 16);
            }
            #pragma unroll
            for (int mf = 0; mf < 2; mf++) {
                int m = warp * 32 + mf * 16 + gid;
                const char* aph0 = smem + SO_AHI + m * (AST * 2) + kb;
                const char* aph1 = aph0 + 8 * (AST * 2);
                uint32_t ah0 = *(const uint32_t*)(aph0);
                uint32_t ah1 = *(const uint32_t*)(aph1);
                uint32_t ah2 = *(const uint32_t*)(aph0 + 16);
                uint32_t ah3 = *(const uint32_t*)(aph1 + 16);
                const char* apl0 = smem + SO_ALO + m * (AST * 2) + kb;
                const char* apl1 = apl0 + 8 * (AST * 2);
                uint32_t al0 = *(const uint32_t*)(apl0);
                uint32_t al1 = *(const uint32_t*)(apl1);
                uint32_t al2 = *(const uint32_t*)(apl0 + 16);
                uint32_t al3 = *(const uint32_t*)(apl1 + 16);
                #pragma unroll
                for (int nf = 0; nf < 10; nf++) {
                    mma16816(c[mf][nf], ah0, ah1, ah2, ah3, bh[nf][0], bh[nf][1]);
                    mma16816(c[mf][nf], ah0, ah1, ah2, ah3, bl[nf][0], bl[nf][1]);
                    mma16816(c[mf][nf], al0, al1, al2, al3, bh[nf][0], bh[nf][1]);
                }
            }
        }
        __syncthreads();

        // ---- epilogue: frags -> cstg PERMUTED + bias, then coalesced stream-out ----
        float* cw = (float*)(smem + SO_CSTG + warp * (32 * CST * 4));
        #pragma unroll
        for (int mf = 0; mf < 2; mf++) {
            int row0 = mf * 16 + gid;
            #pragma unroll
            for (int nf = 0; nf < 10; nf++) {
                float bx = bias_r[nf].x, by = bias_r[nf].y;
                cw[ row0      * CST + ipa[nf]] = c[mf][nf][0] + bx;
                cw[ row0      * CST + ipb[nf]] = c[mf][nf][1] + by;
                cw[(row0 + 8) * CST + ipa[nf]] = c[mf][nf][2] + bx;
                cw[(row0 + 8) * CST + ipb[nf]] = c[mf][nf][3] + by;
            }
        }
        __syncwarp();
        {
            float4* dstw = (float4*)(g_xg + ((size_t)tile * M_TILE + warp * 32) * NGATE);
            #pragma unroll
            for (int i = 0; i < 20; i++) {
                int k = i * 32 + lane;
                int row = k / 20;
                int c4 = k - row * 20;
                float4 v4 = *(const float4*)(cw + row * CST + c4 * 4);
                dstw[k] = v4;
            }
        }
        __syncthreads();
    }
}

// ================= recurrent kernel v2: 2 elems/thread, 4-way gate split =================
#define RCTA     128
#define ELEMS_CTA 64          // 32 pairs x 2 elems
#define R_GRID   (B_TOTAL / ELEMS_CTA)   // 2048
#define HS2_STR  33           // float2 row stride (32 pairs + 1 pad)

struct __align__(16) SMR {
    float w0h[H * 80];
    float w1x[H * 80];
    float w1h[H * 80];
    float bias1[80];
    float wfc[2 * H];
    float bfc[2];
    float2 hs0[H * HS2_STR];
    float2 hs1[H * HS2_STR];
};

__device__ __forceinline__ ull ffma2(ull a, ull b, ull c) {
    ull d;
    asm("fma.rn.f32x2 %0, %1, %2, %3;" : "=l"(d) : "l"(a), "l"(b), "l"(c));
    return d;
}
__device__ __forceinline__ ull pack2(float x) {
    ull r;
    asm("mov.b64 %0, {%1, %1};" : "=l"(r) : "f"(x));
    return r;
}
__device__ __forceinline__ ull packxy(float x, float y) {
    ull r;
    asm("mov.b64 %0, {%1, %2};" : "=l"(r) : "f"(x), "f"(y));
    return r;
}
__device__ __forceinline__ float getf(const ull* acc, int idx) {
    ull v = acc[idx >> 1];
    unsigned u = (idx & 1) ? (unsigned)(v >> 32) : (unsigned)(v & 0xffffffffu);
    return __uint_as_float(u);
}
__device__ __forceinline__ float sig_(float x) {
    return __fdividef(1.0f, 1.0f + __expf(-x));
}
__device__ __forceinline__ float tanh_(float x) {
    float a = fabsf(x);
    float e = __expf(a + a);
    float r = 1.0f - __fdividef(2.0f, e + 1.0f);
    return copysignf(r, x);
}

// acc += w_row * broadcast(x) for 2 elems over this lane's 20 outputs.
// 5 LDS.128, 20 FFMA2.
__device__ __forceinline__ void accum2(ull* a0, ull* a1,
                                       const ulonglong2* __restrict__ w,
                                       ull x0, ull x1) {
    #pragma unroll
    for (int c = 0; c < 5; c++) {
        ulonglong2 wc = w[c];
        a0[2*c]   = ffma2(wc.x, x0, a0[2*c]);
        a0[2*c+1] = ffma2(wc.y, x0, a0[2*c+1]);
        a1[2*c]   = ffma2(wc.x, x1, a1[2*c]);
        a1[2*c+1] = ffma2(wc.y, x1, a1[2*c+1]);
    }
}

__global__ void __launch_bounds__(RCTA, 4) lstm2_rec_kernel(
    const float* __restrict__ Whh0,
    const float* __restrict__ Wih1, const float* __restrict__ Whh1,
    const float* __restrict__ bih1, const float* __restrict__ bhh1,
    const float* __restrict__ Wfc,  const float* __restrict__ bfc,
    float* __restrict__ out)
{
    extern __shared__ unsigned char smraw[];
    SMR* sm = reinterpret_cast<SMR*>(smraw);
    const int tid = threadIdx.x;

    // ---- stage weights (same layout as R10: [k][ j = v*20 + gate*5 + ul ]) ----
    #pragma unroll 1
    for (int idx = tid; idx < H * 80; idx += RCTA) {
        int d = idx / 80, rem = idx - d * 80;
        int v = rem / 20, o = rem - v * 20;
        int row = (o / 5) * 20 + v * 5 + (o % 5);
        sm->w0h[idx] = Whh0[row * H + d];
        sm->w1x[idx] = Wih1[row * H + d];
        sm->w1h[idx] = Whh1[row * H + d];
    }
    if (tid < 80) {
        int v = tid / 20, o = tid - v * 20;
        int row = (o / 5) * 20 + v * 5 + (o % 5);
        sm->bias1[tid] = bih1[row] + bhh1[row];
    }
    if (tid < 2 * H) sm->wfc[tid] = Wfc[tid];
    if (tid < 2)     sm->bfc[tid] = bfc[tid];

    const int p = tid >> 2;     // pair 0..31
    const int v = tid & 3;      // gate-quarter

    // zero h state: lane (p,v) owns rows v*5+ul, col p
    #pragma unroll
    for (int ul = 0; ul < 5; ul++) {
        sm->hs0[(v * 5 + ul) * HS2_STR + p] = make_float2(0.f, 0.f);
        sm->hs1[(v * 5 + ul) * HS2_STR + p] = make_float2(0.f, 0.f);
    }
    __syncthreads();

    const int bg = blockIdx.x * ELEMS_CTA + p * 2;
    const float* xg0 = g_xg + ((size_t)(bg + 0) * T_STEPS) * NGATE + v * 20;
    const float* xg1 = g_xg + ((size_t)(bg + 1) * T_STEPS) * NGATE + v * 20;

    const ulonglong2* w0h = reinterpret_cast<const ulonglong2*>(sm->w0h);
    const ulonglong2* w1x = reinterpret_cast<const ulonglong2*>(sm->w1x);
    const ulonglong2* w1h = reinterpret_cast<const ulonglong2*>(sm->w1h);
    const ulonglong2* bias1 = reinterpret_cast<const ulonglong2*>(sm->bias1) + v * 5;
    float2* hs0 = sm->hs0;
    float2* hs1 = sm->hs1;

    float c0[10], c1[10];       // [e*5 + ul]
    #pragma unroll
    for (int i = 0; i < 10; i++) { c0[i] = 0.f; c1[i] = 0.f; }

    ull a0[10], a1[10];

    #pragma unroll 1
    for (int t = 0; t < T_STEPS; t++) {
        // ===== layer 0: acc = xg (bias folded in GEMM) =====
        {
            const float4* q0 = (const float4*)(xg0 + t * NGATE);
            const float4* q1 = (const float4*)(xg1 + t * NGATE);
            #pragma unroll
            for (int u = 0; u < 5; u++) {
                float4 f0 = q0[u], f1 = q1[u];
                a0[2*u] = packxy(f0.x, f0.y); a0[2*u+1] = packxy(f0.z, f0.w);
                a1[2*u] = packxy(f1.x, f1.y); a1[2*u+1] = packxy(f1.z, f1.w);
            }
        }
        #pragma unroll 4
        for (int k = 0; k < H; k++) {
            float2 hv = hs0[k * HS2_STR + p];
            accum2(a0, a1, w0h + k * 20 + v * 5, pack2(hv.x), pack2(hv.y));
        }
        #pragma unroll
        for (int ul = 0; ul < 5; ul++) {
            float ha, hb;
            {
                float iv = sig_ (getf(a0,      ul));
                float fv = sig_ (getf(a0,  5 + ul));
                float gv = tanh_(getf(a0, 10 + ul));
                float ov = sig_ (getf(a0, 15 + ul));
                float cn = fv * c0[ul] + iv * gv;
                c0[ul] = cn;
                ha = ov * tanh_(cn);
            }
            {
                float iv = sig_ (getf(a1,      ul));
                float fv = sig_ (getf(a1,  5 + ul));
                float gv = tanh_(getf(a1, 10 + ul));
                float ov = sig_ (getf(a1, 15 + ul));
                float cn = fv * c0[5 + ul] + iv * gv;
                c0[5 + ul] = cn;
                hb = ov * tanh_(cn);
            }
            hs0[(v * 5 + ul) * HS2_STR + p] = make_float2(ha, hb);
        }
        __syncwarp();

        // ===== layer 1 =====
        #pragma unroll
        for (int c = 0; c < 5; c++) {
            ulonglong2 bb = bias1[c];
            a0[2*c] = bb.x; a0[2*c+1] = bb.y;
            a1[2*c] = bb.x; a1[2*c+1] = bb.y;
        }
        #pragma unroll 4
        for (int k = 0; k < H; k++) {
            float2 hv = hs0[k * HS2_STR + p];
            accum2(a0, a1, w1x + k * 20 + v * 5, pack2(hv.x), pack2(hv.y));
        }
        #pragma unroll 4
        for (int k = 0; k < H; k++) {
            float2 hv = hs1[k * HS2_STR + p];
            accum2(a0, a1, w1h + k * 20 + v * 5, pack2(hv.x), pack2(hv.y));
        }
        #pragma unroll
        for (int ul = 0; ul < 5; ul++) {
            float ha, hb;
            {
                float iv = sig_ (getf(a0,      ul));
                float fv = sig_ (getf(a0,  5 + ul));
                float gv = tanh_(getf(a0, 10 + ul));
                float ov = sig_ (getf(a0, 15 + ul));
                float cn = fv * c1[ul] + iv * gv;
                c1[ul] = cn;
                ha = ov * tanh_(cn);
            }
            {
                float iv = sig_ (getf(a1,      ul));
                float fv = sig_ (getf(a1,  5 + ul));
                float gv = tanh_(getf(a1, 10 + ul));
                float ov = sig_ (getf(a1, 15 + ul));
                float cn = fv * c1[5 + ul] + iv * gv;
                c1[5 + ul] = cn;
                hb = ov * tanh_(cn);
            }
            hs1[(v * 5 + ul) * HS2_STR + p] = make_float2(ha, hb);
        }
        __syncwarp();
    }

    // ---- FC + softmax(2): lanes v=0,1 handle elems bg+0, bg+1 ----
    if (v < 2) {
        float l0 = sm->bfc[0], l1 = sm->bfc[1];
        #pragma unroll
        for (int k = 0; k < H; k++) {
            float2 hq = hs1[k * HS2_STR + p];
            float hk = v ? hq.y : hq.x;
            l0 += sm->wfc[k]     * hk;
            l1 += sm->wfc[H + k] * hk;
        }
        float p0 = sig_(l0 - l1);
        reinterpret_cast<float2*>(out)[bg + v] = make_float2(p0, 1.0f - p0);
    }
}

// ---------------- launch ----------------
extern "C" void kernel_launch(void* const* d_in, const int* in_sizes, int n_in,
                              void* d_out, int out_size) {
    const float* x    = (const float*)d_in[0];
    const float* Wih0 = (const float*)d_in[1];
    const float* Whh0 = (const float*)d_in[2];
    const float* bih0 = (const float*)d_in[3];
    const float* bhh0 = (const float*)d_in[4];
    const float* Wih1 = (const float*)d_in[5];
    const float* Whh1 = (const float*)d_in[6];
    const float* bih1 = (const float*)d_in[7];
    const float* bhh1 = (const float*)d_in[8];
    const float* Wfc  = (const float*)d_in[9];
    const float* bfc  = (const float*)d_in[10];
    float* out = (float*)d_out;

    cudaFuncSetAttribute(xg_gemm_kernel, cudaFuncAttributeMaxDynamicSharedMemorySize, G_SMEM);
    xg_gemm_kernel<<<G_GRID, G_CTA, G_SMEM>>>(x, Wih0, bih0, bhh0);

    const size_t smem2 = sizeof(SMR);
    cudaFuncSetAttribute(lstm2_rec_kernel, cudaFuncAttributeMaxDynamicSharedMemorySize, (int)smem2);
    lstm2_rec_kernel<<<R_GRID, RCTA, smem2>>>(
        Whh0, Wih1, Whh1, bih1, bhh1, Wfc, bfc, out);
}

// round 12
// speedup vs baseline: 1.1453x; 1.1453x over previous
#include <cuda_runtime.h>
#include <cuda_bf16.h>
#include <cstdint>

typedef unsigned long long ull;

#define B_TOTAL 131072
#define T_STEPS 30
#define DIN     88
#define H       20
#define NGATE   80

// ================= GEMM (layer-0 input projection, HMMA, persistent) =================
#define M_ROWS   (B_TOTAL * T_STEPS)      // 3932160
#define M_TILE   64
#define N_TILES  (M_ROWS / M_TILE)        // 61440
#define G_GRID   444                      // 3 CTAs/SM persistent
#define G_CTA    128
#define AST      104                      // A smem row stride in bf16 (208 B)
#define BST      104
#define CST      84                       // C stage row stride in f32 (336 B)

// smem byte offsets (M_TILE=64)
#define SO_AHI   512                      // 64 x 208 = 13312
#define SO_ALO   (SO_AHI + 13312)         // 13824
#define SO_BHI   (SO_ALO + 13312)         // 27136
#define SO_BLO   (SO_BHI + 16640)         // 43776
#define G_SMEM   (SO_BLO + 16640)         // 60416  (3 CTAs/SM = 181KB)
#define SO_CSTG  SO_AHI                   // C stage aliases A (dead after MMA); 64*336=21504 < 26624

// 1.26 GB scratch for xg[b*T + t][80] (rec-kernel gate order), fp32
__device__ float g_xg[(size_t)M_ROWS * NGATE];

// ---------------- helpers ----------------
__device__ __forceinline__ void split4(float4 f, ull& hi4, ull& lo4) {
    __nv_bfloat16 hx = __float2bfloat16_rn(f.x);
    __nv_bfloat16 hy = __float2bfloat16_rn(f.y);
    __nv_bfloat16 hz = __float2bfloat16_rn(f.z);
    __nv_bfloat16 hw = __float2bfloat16_rn(f.w);
    __nv_bfloat16 lx = __float2bfloat16_rn(f.x - __bfloat162float(hx));
    __nv_bfloat16 ly = __float2bfloat16_rn(f.y - __bfloat162float(hy));
    __nv_bfloat16 lz = __float2bfloat16_rn(f.z - __bfloat162float(hz));
    __nv_bfloat16 lw = __float2bfloat16_rn(f.w - __bfloat162float(hw));
    hi4 = (ull)__bfloat16_as_ushort(hx) | ((ull)__bfloat16_as_ushort(hy) << 16)
        | ((ull)__bfloat16_as_ushort(hz) << 32) | ((ull)__bfloat16_as_ushort(hw) << 48);
    lo4 = (ull)__bfloat16_as_ushort(lx) | ((ull)__bfloat16_as_ushort(ly) << 16)
        | ((ull)__bfloat16_as_ushort(lz) << 32) | ((ull)__bfloat16_as_ushort(lw) << 48);
}

__device__ __forceinline__ void mma16816(float* d,
                                         uint32_t a0, uint32_t a1, uint32_t a2, uint32_t a3,
                                         uint32_t b0, uint32_t b1) {
    asm volatile(
        "mma.sync.aligned.m16n8k16.row.col.f32.bf16.bf16.f32 "
        "{%0,%1,%2,%3}, {%4,%5,%6,%7}, {%8,%9}, {%0,%1,%2,%3};"
        : "+f"(d[0]), "+f"(d[1]), "+f"(d[2]), "+f"(d[3])
        : "r"(a0), "r"(a1), "r"(a2), "r"(a3), "r"(b0), "r"(b1));
}

// natural gate row n -> rec-layout position j
__device__ __forceinline__ int inv_perm(int n) {
    int g2 = n / 20, r = n % 20, v = r / 5, u = r % 5;
    return v * 20 + g2 * 5 + u;
}

// ---------------- persistent GEMM kernel (M_TILE=64, 3 CTAs/SM) ----------------
__global__ void __launch_bounds__(G_CTA, 3)
xg_gemm_kernel(const float* __restrict__ x, const float* __restrict__ Wih0,
               const float* __restrict__ bih0, const float* __restrict__ bhh0)
{
    extern __shared__ char smem[];
    const int tid = threadIdx.x;
    const int warp = tid >> 5, lane = tid & 31;
    const int gid = lane >> 2, tg = lane & 3;

    // ---- one-time: B hi/lo staging (natural gate-row order) ----
    if (tid < NGATE) {
        char* bhi = smem + SO_BHI + tid * (BST * 2);
        char* blo = smem + SO_BLO + tid * (BST * 2);
        const float4* wr = (const float4*)(Wih0 + tid * DIN);
        float4 wv[22];
        #pragma unroll
        for (int q = 0; q < 22; q++) wv[q] = wr[q];
        #pragma unroll
        for (int q = 0; q < 22; q++) {
            ull hi4, lo4;
            split4(wv[q], hi4, lo4);
            *(ull*)(bhi + q * 8) = hi4;
            *(ull*)(blo + q * 8) = lo4;
        }
        *(ull*)(bhi + 176) = 0; *(ull*)(bhi + 184) = 0;
        *(ull*)(blo + 176) = 0; *(ull*)(blo + 184) = 0;
    }

    // ---- per-thread constants: bias + inv-perm offsets ----
    float2 bias_r[10];
    int ipa[10], ipb[10];
    #pragma unroll
    for (int nf = 0; nf < 10; nf++) {
        int n0 = nf * 8 + tg * 2;
        bias_r[nf] = make_float2(bih0[n0] + bhh0[n0], bih0[n0 + 1] + bhh0[n0 + 1]);
        ipa[nf] = inv_perm(n0);
        ipb[nf] = inv_perm(n0 + 1);
    }

    // ---- coalesced prefetch of first tile (64 rows x 22 float4 = 1408) ----
    int tile = blockIdx.x;
    float4 xr[11];
    if (tile < N_TILES) {
        const float4* xp = (const float4*)(x + (size_t)tile * M_TILE * DIN);
        #pragma unroll
        for (int q = 0; q < 11; q++) xr[q] = xp[q * 128 + tid];
    }
    __syncthreads();

    #pragma unroll 1
    for (; tile < N_TILES; tile += G_GRID) {
        // ---- phase 1: split + scatter-store A ----
        #pragma unroll
        for (int q = 0; q < 11; q++) {
            int e = q * 512 + tid * 4;          // element index within 64x88 tile
            int r = e / 88;
            int cc = e - r * 88;
            int addr = r * (AST * 2) + cc * 2;
            ull hi4, lo4;
            split4(xr[q], hi4, lo4);
            *(ull*)(smem + SO_AHI + addr) = hi4;
            *(ull*)(smem + SO_ALO + addr) = lo4;
        }
        // re-zero pads (cstg alias clobbers them): thread tid<64 owns row tid
        if (tid < M_TILE) {
            char* ah = smem + SO_AHI + tid * (AST * 2);
            char* al = smem + SO_ALO + tid * (AST * 2);
            *(ull*)(ah + 176) = 0; *(ull*)(ah + 184) = 0;
            *(ull*)(al + 176) = 0; *(ull*)(al + 184) = 0;
        }
        __syncthreads();

        // ---- phase 2: coalesced prefetch of next tile (overlaps MMA) ----
        {
            int nxt = tile + G_GRID;
            if (nxt < N_TILES) {
                const float4* xp = (const float4*)(x + (size_t)nxt * M_TILE * DIN);
                #pragma unroll
                for (int q = 0; q < 11; q++) xr[q] = xp[q * 128 + tid];
            }
        }

        // ---- MMA mainloop: 6 ko steps, each fragment loaded ONCE ----
        float c[10][4];
        #pragma unroll
        for (int nf = 0; nf < 10; nf++)
            #pragma unroll
            for (int q = 0; q < 4; q++) c[nf][q] = 0.f;

        #pragma unroll 1
        for (int ko6 = 0; ko6 < 6; ko6++) {
            const int kb = (ko6 * 16 + tg * 2) * 2;

            uint32_t bh[10][2], bl[10][2];
            #pragma unroll
            for (int nf = 0; nf < 10; nf++) {
                int n = nf * 8 + gid;
                const char* bph = smem + SO_BHI + n * (BST * 2) + kb;
                const char* bpl = smem + SO_BLO + n * (BST * 2) + kb;
                bh[nf][0] = *(const uint32_t*)(bph);
                bh[nf][1] = *(const uint32_t*)(bph + 16);
                bl[nf][0] = *(const uint32_t*)(bpl);
                bl[nf][1] = *(const uint32_t*)(bpl + 16);
            }
            {
                int m = warp * 16 + gid;
                const char* aph0 = smem + SO_AHI + m * (AST * 2) + kb;
                const char* aph1 = aph0 + 8 * (AST * 2);
                uint32_t ah0 = *(const uint32_t*)(aph0);
                uint32_t ah1 = *(const uint32_t*)(aph1);
                uint32_t ah2 = *(const uint32_t*)(aph0 + 16);
                uint32_t ah3 = *(const uint32_t*)(aph1 + 16);
                const char* apl0 = smem + SO_ALO + m * (AST * 2) + kb;
                const char* apl1 = apl0 + 8 * (AST * 2);
                uint32_t al0 = *(const uint32_t*)(apl0);
                uint32_t al1 = *(const uint32_t*)(apl1);
                uint32_t al2 = *(const uint32_t*)(apl0 + 16);
                uint32_t al3 = *(const uint32_t*)(apl1 + 16);
                #pragma unroll
                for (int nf = 0; nf < 10; nf++) {
                    mma16816(c[nf], ah0, ah1, ah2, ah3, bh[nf][0], bh[nf][1]);
                    mma16816(c[nf], ah0, ah1, ah2, ah3, bl[nf][0], bl[nf][1]);
                    mma16816(c[nf], al0, al1, al2, al3, bh[nf][0], bh[nf][1]);
                }
            }
        }
        __syncthreads();   // all warps done reading A -> safe to alias as C stage

        // ---- epilogue: frags -> cstg PERMUTED + bias, coalesced stream-out ----
        float* cw = (float*)(smem + SO_CSTG) + warp * (16 * CST);
        #pragma unroll
        for (int nf = 0; nf < 10; nf++) {
            float bx = bias_r[nf].x, by = bias_r[nf].y;
            cw[ gid      * CST + ipa[nf]] = c[nf][0] + bx;
            cw[ gid      * CST + ipb[nf]] = c[nf][1] + by;
            cw[(gid + 8) * CST + ipa[nf]] = c[nf][2] + bx;
            cw[(gid + 8) * CST + ipb[nf]] = c[nf][3] + by;
        }
        __syncwarp();
        {
            // warp's 16 rows x 80 f32 = 320 float4 contiguous in g_xg
            float4* dstw = (float4*)(g_xg + ((size_t)tile * M_TILE + warp * 16) * NGATE);
            #pragma unroll
            for (int i = 0; i < 10; i++) {
                int k = i * 32 + lane;
                int row = k / 20;
                int c4 = k - row * 20;
                float4 v4 = *(const float4*)(cw + row * CST + c4 * 4);
                dstw[k] = v4;
            }
        }
        __syncthreads();   // cstg reads done before next tile's A scatter-store
    }
}

// ================= recurrent kernel (EXACT R10 version, 1012us measured) =================
#define CTA     128
#define HS_STR  33

struct __align__(16) SMR {
    float w0h[H * 80];
    float w1x[H * 80];
    float w1h[H * 80];
    float bias1[80];
    float wfc[2 * H];
    float bfc[2];
    float4 hs0[H * HS_STR];
    float4 hs1[H * HS_STR];
};

__device__ __forceinline__ ull ffma2(ull a, ull b, ull c) {
    ull d;
    asm("fma.rn.f32x2 %0, %1, %2, %3;" : "=l"(d) : "l"(a), "l"(b), "l"(c));
    return d;
}
__device__ __forceinline__ ull pack2(float x) {
    ull r;
    asm("mov.b64 %0, {%1, %1};" : "=l"(r) : "f"(x));
    return r;
}
__device__ __forceinline__ ull packxy(float x, float y) {
    ull r;
    asm("mov.b64 %0, {%1, %2};" : "=l"(r) : "f"(x), "f"(y));
    return r;
}
__device__ __forceinline__ float getf(const ull* acc, int idx) {
    ull v = acc[idx >> 1];
    unsigned u = (idx & 1) ? (unsigned)(v >> 32) : (unsigned)(v & 0xffffffffu);
    return __uint_as_float(u);
}
__device__ __forceinline__ float sig_(float x) {
    return __fdividef(1.0f, 1.0f + __expf(-x));
}
__device__ __forceinline__ float tanh_(float x) {
    float a = fabsf(x);
    float e = __expf(a + a);
    float r = 1.0f - __fdividef(2.0f, e + 1.0f);
    return copysignf(r, x);
}
__device__ __forceinline__ void accum4(ull* a, const ulonglong2* __restrict__ w,
                                       ull x0, ull x1, ull x2, ull x3) {
    #pragma unroll
    for (int c = 0; c < 5; c++) {
        ulonglong2 wc = w[c];
        a[ 0 + 2*c]   = ffma2(wc.x, x0, a[ 0 + 2*c]);
        a[ 0 + 2*c+1] = ffma2(wc.y, x0, a[ 0 + 2*c+1]);
        a[10 + 2*c]   = ffma2(wc.x, x1, a[10 + 2*c]);
        a[10 + 2*c+1] = ffma2(wc.y, x1, a[10 + 2*c+1]);
        a[20 + 2*c]   = ffma2(wc.x, x2, a[20 + 2*c]);
        a[20 + 2*c+1] = ffma2(wc.y, x2, a[20 + 2*c+1]);
        a[30 + 2*c]   = ffma2(wc.x, x3, a[30 + 2*c]);
        a[30 + 2*c+1] = ffma2(wc.y, x3, a[30 + 2*c+1]);
    }
}

__global__ void __launch_bounds__(CTA, 3) lstm2_rec_kernel(
    const float* __restrict__ Whh0,
    const float* __restrict__ Wih1, const float* __restrict__ Whh1,
    const float* __restrict__ bih1, const float* __restrict__ bhh1,
    const float* __restrict__ Wfc,  const float* __restrict__ bfc,
    float* __restrict__ out)
{
    extern __shared__ unsigned char smraw[];
    SMR* sm = reinterpret_cast<SMR*>(smraw);
    const int tid = threadIdx.x;

    #pragma unroll 1
    for (int idx = tid; idx < H * 80; idx += CTA) {
        int d = idx / 80, rem = idx - d * 80;
        int v = rem / 20, o = rem - v * 20;
        int row = (o / 5) * 20 + v * 5 + (o % 5);
        sm->w0h[idx] = Whh0[row * H + d];
        sm->w1x[idx] = Wih1[row * H + d];
        sm->w1h[idx] = Whh1[row * H + d];
    }
    if (tid < 80) {
        int v = tid / 20, o = tid - v * 20;
        int row = (o / 5) * 20 + v * 5 + (o % 5);
        sm->bias1[tid] = bih1[row] + bhh1[row];
    }
    if (tid < 2 * H) sm->wfc[tid] = Wfc[tid];
    if (tid < 2)     sm->bfc[tid] = bfc[tid];

    const int g = tid >> 2;
    const int v = tid & 3;

    #pragma unroll
    for (int ul = 0; ul < 5; ul++) {
        sm->hs0[(v * 5 + ul) * HS_STR + g] = make_float4(0.f, 0.f, 0.f, 0.f);
        sm->hs1[(v * 5 + ul) * HS_STR + g] = make_float4(0.f, 0.f, 0.f, 0.f);
    }
    __syncthreads();

    const int bg = blockIdx.x * CTA + g * 4;
    const float* xg0 = g_xg + ((size_t)(bg + 0) * T_STEPS) * NGATE + v * 20;
    const float* xg1 = g_xg + ((size_t)(bg + 1) * T_STEPS) * NGATE + v * 20;
    const float* xg2 = g_xg + ((size_t)(bg + 2) * T_STEPS) * NGATE + v * 20;
    const float* xg3 = g_xg + ((size_t)(bg + 3) * T_STEPS) * NGATE + v * 20;

    const ulonglong2* w0h = reinterpret_cast<const ulonglong2*>(sm->w0h);
    const ulonglong2* w1x = reinterpret_cast<const ulonglong2*>(sm->w1x);
    const ulonglong2* w1h = reinterpret_cast<const ulonglong2*>(sm->w1h);
    const ulonglong2* bias1 = reinterpret_cast<const ulonglong2*>(sm->bias1) + v * 5;
    float4* hs0 = sm->hs0;
    float4* hs1 = sm->hs1;

    float c0[20], c1[20];
    #pragma unroll
    for (int i = 0; i < 20; i++) { c0[i] = 0.f; c1[i] = 0.f; }

    ull a[40];

    #pragma unroll 1
    for (int t = 0; t < T_STEPS; t++) {
        // ===== layer 0: acc = xg (bias folded in GEMM) =====
        {
            const float4* p0 = (const float4*)(xg0 + t * NGATE);
            const float4* p1 = (const float4*)(xg1 + t * NGATE);
            const float4* p2 = (const float4*)(xg2 + t * NGATE);
            const float4* p3 = (const float4*)(xg3 + t * NGATE);
            #pragma unroll
            for (int u = 0; u < 5; u++) {
                float4 q0 = p0[u], q1 = p1[u], q2 = p2[u], q3 = p3[u];
                a[      2*u] = packxy(q0.x, q0.y); a[      2*u+1] = packxy(q0.z, q0.w);
                a[10 +  2*u] = packxy(q1.x, q1.y); a[10 +  2*u+1] = packxy(q1.z, q1.w);
                a[20 +  2*u] = packxy(q2.x, q2.y); a[20 +  2*u+1] = packxy(q2.z, q2.w);
                a[30 +  2*u] = packxy(q3.x, q3.y); a[30 +  2*u+1] = packxy(q3.z, q3.w);
            }
        }
        #pragma unroll 4
        for (int k = 0; k < H; k++) {
            float4 hv = hs0[k * HS_STR + g];
            accum4(a, w0h + k * 20 + v * 5,
                   pack2(hv.x), pack2(hv.y), pack2(hv.z), pack2(hv.w));
        }
        #pragma unroll
        for (int ul = 0; ul < 5; ul++) {
            float hv[4];
            #pragma unroll
            for (int e = 0; e < 4; e++) {
                const ull* ae = a + e * 10;
                float iv = sig_ (getf(ae,      ul));
                float fv = sig_ (getf(ae,  5 + ul));
                float gv = tanh_(getf(ae, 10 + ul));
                float ov = sig_ (getf(ae, 15 + ul));
                float cn = fv * c0[e*5 + ul] + iv * gv;
                c0[e*5 + ul] = cn;
                hv[e] = ov * tanh_(cn);
            }
            hs0[(v * 5 + ul) * HS_STR + g] = make_float4(hv[0], hv[1], hv[2], hv[3]);
        }
        __syncwarp();

        // ===== layer 1 =====
        #pragma unroll
        for (int c = 0; c < 5; c++) {
            ulonglong2 bb = bias1[c];
            a[2*c] = bb.x; a[2*c+1] = bb.y;
            a[10+2*c] = bb.x; a[10+2*c+1] = bb.y;
            a[20+2*c] = bb.x; a[20+2*c+1] = bb.y;
            a[30+2*c] = bb.x; a[30+2*c+1] = bb.y;
        }
        #pragma unroll 4
        for (int k = 0; k < H; k++) {
            float4 hv = hs0[k * HS_STR + g];
            accum4(a, w1x + k * 20 + v * 5,
                   pack2(hv.x), pack2(hv.y), pack2(hv.z), pack2(hv.w));
        }
        #pragma unroll 4
        for (int k = 0; k < H; k++) {
            float4 hv = hs1[k * HS_STR + g];
            accum4(a, w1h + k * 20 + v * 5,
                   pack2(hv.x), pack2(hv.y), pack2(hv.z), pack2(hv.w));
        }
        #pragma unroll
        for (int ul = 0; ul < 5; ul++) {
            float hv[4];
            #pragma unroll
            for (int e = 0; e < 4; e++) {
                const ull* ae = a + e * 10;
                float iv = sig_ (getf(ae,      ul));
                float fv = sig_ (getf(ae,  5 + ul));
                float gv = tanh_(getf(ae, 10 + ul));
                float ov = sig_ (getf(ae, 15 + ul));
                float cn = fv * c1[e*5 + ul] + iv * gv;
                c1[e*5 + ul] = cn;
                hv[e] = ov * tanh_(cn);
            }
            hs1[(v * 5 + ul) * HS_STR + g] = make_float4(hv[0], hv[1], hv[2], hv[3]);
        }
        __syncwarp();
    }

    // ---- FC + softmax(2) ----
    float l0 = sm->bfc[0], l1 = sm->bfc[1];
    #pragma unroll
    for (int k = 0; k < H; k++) {
        float4 hq = hs1[k * HS_STR + g];
        float hk = (v == 0) ? hq.x : (v == 1) ? hq.y : (v == 2) ? hq.z : hq.w;
        l0 += sm->wfc[k]     * hk;
        l1 += sm->wfc[H + k] * hk;
    }
    float p0 = sig_(l0 - l1);
    reinterpret_cast<float2*>(out)[bg + v] = make_float2(p0, 1.0f - p0);
}

// ---------------- launch ----------------
extern "C" void kernel_launch(void* const* d_in, const int* in_sizes, int n_in,
                              void* d_out, int out_size) {
    const float* x    = (const float*)d_in[0];
    const float* Wih0 = (const float*)d_in[1];
    const float* Whh0 = (const float*)d_in[2];
    const float* bih0 = (const float*)d_in[3];
    const float* bhh0 = (const float*)d_in[4];
    const float* Wih1 = (const float*)d_in[5];
    const float* Whh1 = (const float*)d_in[6];
    const float* bih1 = (const float*)d_in[7];
    const float* bhh1 = (const float*)d_in[8];
    const float* Wfc  = (const float*)d_in[9];
    const float* bfc  = (const float*)d_in[10];
    float* out = (float*)d_out;

    cudaFuncSetAttribute(xg_gemm_kernel, cudaFuncAttributeMaxDynamicSharedMemorySize, G_SMEM);
    xg_gemm_kernel<<<G_GRID, G_CTA, G_SMEM>>>(x, Wih0, bih0, bhh0);

    const size_t smem2 = sizeof(SMR);
    cudaFuncSetAttribute(lstm2_rec_kernel, cudaFuncAttributeMaxDynamicSharedMemorySize, (int)smem2);
    lstm2_rec_kernel<<<B_TOTAL / CTA, CTA, smem2>>>(
        Whh0, Wih1, Whh1, bih1, bhh1, Wfc, bfc, out);
}